// round 10
// baseline (speedup 1.0000x reference)
#include <cuda_runtime.h>
#include <cuda_fp16.h>

// ---------------------------------------------------------------------------
// Mipmapped texture sampling, GB300 — fp16 pyramid (32B/texel, HWC).
// Level i (i>=1) texel = 0.25 * 2x2 of base pixels at y0 = y*2^i + 2^(i-1) - 1
// (exact algebra of align_corners=False bilinear downsample by 2^i), so
// mips are built straight from the fp32 input: no transpose->mips dependency,
// both run in ONE fused launch.
// Sample: big levels (0-2, 10.9MB, L2-resident) loaded with __ldcg (L2-cached,
// no L1 allocation) so levels 3-7 (170KB) stay L1-resident.
// ---------------------------------------------------------------------------

#define NLEV 8

__device__ __align__(16) __half g_pyr[5592320];

__constant__ int c_off[NLEV] = {
    0, 4194304, 5242880, 5505024, 5570560, 5586944, 5591040, 5592064
};

__device__ __forceinline__ float2 u2f2(unsigned u) {
    return __half22float2(*reinterpret_cast<const __half2*>(&u));
}
__device__ __forceinline__ unsigned f2u(float a, float b) {
    __half2 h = __floats2half2_rn(a, b);
    return *reinterpret_cast<const unsigned*>(&h);
}
__device__ __forceinline__ float f2get(const float2& v, int j) {
    return j == 0 ? v.x : v.y;
}

// ---------------------------------------------------------------------------
// Fused prep kernel.
// Blocks [0, 1024):   transpose. 262,144 threads, thread = (pixel-pair,
//                     channel-half): 8 x LDG.64 plane loads, 2 x STG.128.
// Blocks [1024, 1707): mips. 174,752 threads, thread = (texel, channel-half):
//                     level texel = 0.25 * 2x2 of base fp32 pixels.
// No dependency between the halves; sample kernel launches after both.
// ---------------------------------------------------------------------------
__global__ void k_prep(const float* __restrict__ tex) {
    const int plane = 512 * 512;
    if (blockIdx.x < 1024) {
        int idx = blockIdx.x * blockDim.x + threadIdx.x;   // < 262144
        int t   = idx & 1;        // 0: channels 0-7, 1: channels 8-15
        int grp = idx >> 1;       // pixel pair index
        const int plane2 = plane / 2;
        const float2* src = reinterpret_cast<const float2*>(tex) + (8 * t) * plane2 + grp;

        float2 v0 = __ldg(src);
        float2 v1 = __ldg(src + plane2);
        float2 v2 = __ldg(src + 2 * plane2);
        float2 v3 = __ldg(src + 3 * plane2);
        float2 v4 = __ldg(src + 4 * plane2);
        float2 v5 = __ldg(src + 5 * plane2);
        float2 v6 = __ldg(src + 6 * plane2);
        float2 v7 = __ldg(src + 7 * plane2);

        uint4* base = reinterpret_cast<uint4*>(g_pyr);
#pragma unroll
        for (int j = 0; j < 2; j++) {
            uint4 a;
            a.x = f2u(f2get(v0, j), f2get(v1, j));
            a.y = f2u(f2get(v2, j), f2get(v3, j));
            a.z = f2u(f2get(v4, j), f2get(v5, j));
            a.w = f2u(f2get(v6, j), f2get(v7, j));
            base[(2 * grp + j) * 2 + t] = a;
        }
    } else {
        int idx = (blockIdx.x - 1024) * blockDim.x + threadIdx.x;
        if (idx >= 2 * 87376) return;
        int t   = idx & 1;
        int rem = idx >> 1;

        int l = 1;
#pragma unroll
        for (int i = 1; i < NLEV; i++) {
            int np = (512 >> i) * (512 >> i);
            if (rem < np) { l = i; break; }
            rem -= np;
        }
        int s  = 512 >> l;
        int x  = rem & (s - 1);
        int y  = rem >> (9 - l);
        int sc = 1 << l;
        int x0 = x * sc + (sc >> 1) - 1;
        int y0 = y * sc + (sc >> 1) - 1;

        const float* src = tex + (8 * t) * plane + y0 * 512 + x0;
#define AVG(c) (0.25f * (__ldg(src + (c) * plane)       + __ldg(src + (c) * plane + 1) + \
                         __ldg(src + (c) * plane + 512) + __ldg(src + (c) * plane + 513)))
        float a0 = AVG(0), a1 = AVG(1), a2 = AVG(2), a3 = AVG(3);
        float a4 = AVG(4), a5 = AVG(5), a6 = AVG(6), a7 = AVG(7);
#undef AVG
        uint4 r;
        r.x = f2u(a0, a1);
        r.y = f2u(a2, a3);
        r.z = f2u(a4, a5);
        r.w = f2u(a6, a7);
        reinterpret_cast<uint4*>(g_pyr + c_off[l])[(y * s + x) * 2 + t] = r;
    }
}

// ---------------------------------------------------------------------------
// Sample kernel. 2 threads/query, 8 channels each (one LDG.128 per texel).
// All 8 loads (both levels) issued before any accumulation (MLP=8).
// Big levels via __ldcg (L2 only); small levels default (L1-resident).
// ---------------------------------------------------------------------------
__device__ __forceinline__ void lvl_setup(int l, float gx, float gy, int t, float lw,
        const uint4*& p00, const uint4*& p01, const uint4*& p10, const uint4*& p11,
        float& w00, float& w01, float& w10, float& w11) {
    int   s  = 512 >> l;
    float fs = (float)(s - 1);
    float x = fminf(fmaxf((gx + 1.0f) * 0.5f * fs, 0.0f), fs);
    float y = fminf(fmaxf((gy + 1.0f) * 0.5f * fs, 0.0f), fs);
    int x0 = (int)x;
    int y0 = (int)y;
    int x1 = min(x0 + 1, s - 1);
    int y1 = min(y0 + 1, s - 1);
    float fx = x - (float)x0;
    float fy = y - (float)y0;

    const uint4* b = reinterpret_cast<const uint4*>(g_pyr + c_off[l]);
    int r0 = y0 * s, r1 = y1 * s;
    p00 = &b[(r0 + x0) * 2 + t];
    p01 = &b[(r0 + x1) * 2 + t];
    p10 = &b[(r1 + x0) * 2 + t];
    p11 = &b[(r1 + x1) * 2 + t];
    w00 = lw * (1.0f - fx) * (1.0f - fy);
    w01 = lw * fx * (1.0f - fy);
    w10 = lw * (1.0f - fx) * fy;
    w11 = lw * fx * fy;
}

__device__ __forceinline__ uint4 ld_pol(const uint4* p, bool big) {
    return big ? __ldcg(p) : __ldg(p);
}

__global__ void k_sample(const float* __restrict__ uv,
                         const float* __restrict__ p,
                         float* __restrict__ out, int N) {
    int idx = blockIdx.x * blockDim.x + threadIdx.x;
    int q = idx >> 1;
    if (q >= N) return;
    int t = idx & 1;

    float2 uvq = __ldg(reinterpret_cast<const float2*>(uv) + q);
    float  pp  = __ldg(&p[q]);

    float lf = pp * (float)(NLEV - 1);
    int   l0 = min((int)lf, NLEV - 1);          // pp >= 0 -> trunc == floor
    int   l1 = min(l0 + 1, NLEV - 1);
    float alpha = lf - (float)l0;

    float gx = 2.0f * uvq.x - 1.0f;
    float gy = 2.0f * uvq.y - 1.0f;

    const uint4 *a00, *a01, *a10, *a11, *b00, *b01, *b10, *b11;
    float wa00, wa01, wa10, wa11, wb00, wb01, wb10, wb11;
    lvl_setup(l0, gx, gy, t, 1.0f - alpha, a00, a01, a10, a11, wa00, wa01, wa10, wa11);
    lvl_setup(l1, gx, gy, t, alpha,        b00, b01, b10, b11, wb00, wb01, wb10, wb11);

    bool big0 = l0 < 3;    // levels 0-2: L2 only, keep L1 for levels 3-7
    bool big1 = l1 < 3;

    // batch all 8 texel loads
    uint4 va0 = ld_pol(a00, big0);
    uint4 va1 = ld_pol(a01, big0);
    uint4 va2 = ld_pol(a10, big0);
    uint4 va3 = ld_pol(a11, big0);
    uint4 vb0 = ld_pol(b00, big1);
    uint4 vb1 = ld_pol(b01, big1);
    uint4 vb2 = ld_pol(b10, big1);
    uint4 vb3 = ld_pol(b11, big1);

    float4 A = make_float4(0.f, 0.f, 0.f, 0.f);
    float4 B = make_float4(0.f, 0.f, 0.f, 0.f);
#define ACC(V, W) {                                                  \
        float2 f0 = u2f2(V.x); A.x += (W) * f0.x; A.y += (W) * f0.y;  \
        float2 f1 = u2f2(V.y); A.z += (W) * f1.x; A.w += (W) * f1.y;  \
        float2 f2 = u2f2(V.z); B.x += (W) * f2.x; B.y += (W) * f2.y;  \
        float2 f3 = u2f2(V.w); B.z += (W) * f3.x; B.w += (W) * f3.y; }
    ACC(va0, wa00) ACC(va1, wa01) ACC(va2, wa10) ACC(va3, wa11)
    ACC(vb0, wb00) ACC(vb1, wb01) ACC(vb2, wb10) ACC(vb3, wb11)
#undef ACC

    // streaming stores: keep the 64MB output from evicting the pyramid in L2
    float4* o = reinterpret_cast<float4*>(out) + q * 4 + t * 2;
    __stcs(o,     A);
    __stcs(o + 1, B);
}

// ---------------------------------------------------------------------------
extern "C" void kernel_launch(void* const* d_in, const int* in_sizes, int n_in,
                              void* d_out, int out_size) {
    const float* uv  = (const float*)d_in[0];
    const float* p   = (const float*)d_in[1];
    const float* tex = (const float*)d_in[2];
    float* out = (float*)d_out;
    int N = in_sizes[1];          // number of queries (p element count)

    // 1024 transpose blocks + ceil(174752/256)=683 mips blocks
    k_prep<<<1707, 256>>>(tex);
    int total = N * 2;
    k_sample<<<(total + 255) / 256, 256>>>(uv, p, out, N);
}

// round 11
// speedup vs baseline: 1.1050x; 1.1050x over previous
#include <cuda_runtime.h>
#include <cuda_fp16.h>

// ---------------------------------------------------------------------------
// Mipmapped texture sampling, GB300 — fp16 pyramid (32B/texel, HWC).
// Level i (i>=1) texel = 0.25 * 2x2 of base pixels at y0 = y*2^i + 2^(i-1) - 1
// (exact algebra of align_corners=False bilinear downsample by 2^i): mips are
// built straight from the fp32 input, fused with the transpose in one launch.
//
// Sample is L1tex-WAVEFRONT bound (measured 65.7% L1): cost = distinct 128B
// line touches. So the x0/x1 texel pair (contiguous 64B) is fetched by ONE
// LDG across 4 lanes per query -> ~5 line touches/query instead of 8.
// x1/y1 are left unclamped; at clamp boundaries their bilinear weight is
// exactly 0, and a zero pad on g_pyr covers the level-7 edge overrun.
// ---------------------------------------------------------------------------

#define NLEV 8

// 5,592,320 pyramid halves + 128 zero-pad halves for weight-0 edge overreads
__device__ __align__(16) __half g_pyr[5592448];

__constant__ int c_off[NLEV] = {
    0, 4194304, 5242880, 5505024, 5570560, 5586944, 5591040, 5592064
};

__device__ __forceinline__ float2 u2f2(unsigned u) {
    return __half22float2(*reinterpret_cast<const __half2*>(&u));
}
__device__ __forceinline__ unsigned f2u(float a, float b) {
    __half2 h = __floats2half2_rn(a, b);
    return *reinterpret_cast<const unsigned*>(&h);
}
__device__ __forceinline__ float f2get(const float2& v, int j) {
    return j == 0 ? v.x : v.y;
}

// ---------------------------------------------------------------------------
// Fused prep kernel.
// Blocks [0,1024):    transpose. thread = (pixel-pair, channel-half):
//                     8 x LDG.64 plane loads, 2 x STG.128.
// Blocks [1024,1707): mips. thread = (texel, channel-half): level texel =
//                     0.25 * 2x2 of base fp32 pixels (reads tex directly).
// ---------------------------------------------------------------------------
__global__ void k_prep(const float* __restrict__ tex) {
    const int plane = 512 * 512;
    if (blockIdx.x < 1024) {
        int idx = blockIdx.x * blockDim.x + threadIdx.x;   // < 262144
        int t   = idx & 1;        // 0: channels 0-7, 1: channels 8-15
        int grp = idx >> 1;       // pixel pair index
        const int plane2 = plane / 2;
        const float2* src = reinterpret_cast<const float2*>(tex) + (8 * t) * plane2 + grp;

        float2 v0 = __ldg(src);
        float2 v1 = __ldg(src + plane2);
        float2 v2 = __ldg(src + 2 * plane2);
        float2 v3 = __ldg(src + 3 * plane2);
        float2 v4 = __ldg(src + 4 * plane2);
        float2 v5 = __ldg(src + 5 * plane2);
        float2 v6 = __ldg(src + 6 * plane2);
        float2 v7 = __ldg(src + 7 * plane2);

        uint4* base = reinterpret_cast<uint4*>(g_pyr);
#pragma unroll
        for (int j = 0; j < 2; j++) {
            uint4 a;
            a.x = f2u(f2get(v0, j), f2get(v1, j));
            a.y = f2u(f2get(v2, j), f2get(v3, j));
            a.z = f2u(f2get(v4, j), f2get(v5, j));
            a.w = f2u(f2get(v6, j), f2get(v7, j));
            base[(2 * grp + j) * 2 + t] = a;
        }
    } else {
        int idx = (blockIdx.x - 1024) * blockDim.x + threadIdx.x;
        if (idx >= 2 * 87376) return;
        int t   = idx & 1;
        int rem = idx >> 1;

        int l = 1;
#pragma unroll
        for (int i = 1; i < NLEV; i++) {
            int np = (512 >> i) * (512 >> i);
            if (rem < np) { l = i; break; }
            rem -= np;
        }
        int s  = 512 >> l;
        int x  = rem & (s - 1);
        int y  = rem >> (9 - l);
        int sc = 1 << l;
        int x0 = x * sc + (sc >> 1) - 1;
        int y0 = y * sc + (sc >> 1) - 1;

        const float* src = tex + (8 * t) * plane + y0 * 512 + x0;
#define AVG(c) (0.25f * (__ldg(src + (c) * plane)       + __ldg(src + (c) * plane + 1) + \
                         __ldg(src + (c) * plane + 512) + __ldg(src + (c) * plane + 513)))
        float a0 = AVG(0), a1 = AVG(1), a2 = AVG(2), a3 = AVG(3);
        float a4 = AVG(4), a5 = AVG(5), a6 = AVG(6), a7 = AVG(7);
#undef AVG
        uint4 r;
        r.x = f2u(a0, a1);
        r.y = f2u(a2, a3);
        r.z = f2u(a4, a5);
        r.w = f2u(a6, a7);
        reinterpret_cast<uint4*>(g_pyr + c_off[l])[(y * s + x) * 2 + t] = r;
    }
}

// ---------------------------------------------------------------------------
// Sample kernel. 4 threads/query. Lane t loads bytes [t*16, t*16+16) of the
// 64B span [texel x0 | texel x1] for each of 4 (level,row) pairs -> 4 LDG.128
// per thread, each warp-LDG touching ~1 line per query (vs 2 before).
//   t = 2*xs + ... actually: xs = t>>1 (x0 vs x1 texel), cg = t&1 (ch 0-7 vs 8-15).
// Cross-lane x0+x1 reduction via shfl_xor(2); 4 lanes store 4 float4 = 64B out.
// ---------------------------------------------------------------------------
__device__ __forceinline__ void lvl_addr(int l, float gx, float gy, int t,
        const uint4*& r0, const uint4*& r1, float& fx, float& fy) {
    int   s  = 512 >> l;
    float fs = (float)(s - 1);
    float x = fminf(fmaxf((gx + 1.0f) * 0.5f * fs, 0.0f), fs);
    float y = fminf(fmaxf((gy + 1.0f) * 0.5f * fs, 0.0f), fs);
    int x0 = (int)x;             // trunc == floor (x >= 0)
    int y0 = (int)y;
    fx = x - (float)x0;          // 0 exactly when x0 would clamp
    fy = y - (float)y0;
    const uint4* b = reinterpret_cast<const uint4*>(g_pyr + c_off[l]);
    r0 = b + (y0 * s + x0) * 2 + t;   // lane t: 16B chunk of the 64B x0|x1 span
    r1 = r0 + 2 * s;                  // row y0+1 (unclamped; weight 0 at edge)
}

__global__ void k_sample(const float* __restrict__ uv,
                         const float* __restrict__ p,
                         float* __restrict__ out, int N) {
    int idx = blockIdx.x * blockDim.x + threadIdx.x;
    int q = idx >> 2;
    if (q >= N) return;
    int t  = idx & 3;
    int xs = t >> 1;      // 0: x0 texel, 1: x1 texel
    int cg = t & 1;       // 0: channels 0-7, 1: channels 8-15

    float2 uvq = __ldg(reinterpret_cast<const float2*>(uv) + q);
    float  pp  = __ldg(&p[q]);

    float lf = pp * (float)(NLEV - 1);
    int   l0 = min((int)lf, NLEV - 1);
    int   l1 = min(l0 + 1, NLEV - 1);
    float alpha = lf - (float)l0;

    float gx = 2.0f * uvq.x - 1.0f;
    float gy = 2.0f * uvq.y - 1.0f;

    const uint4 *a0, *a1, *b0, *b1;
    float fxa, fya, fxb, fyb;
    lvl_addr(l0, gx, gy, t, a0, a1, fxa, fya);
    lvl_addr(l1, gx, gy, t, b0, b1, fxb, fyb);

    // batch all 4 span loads (both levels, both rows)
    uint4 va0 = __ldg(a0);
    uint4 va1 = __ldg(a1);
    uint4 vb0 = __ldg(b0);
    uint4 vb1 = __ldg(b1);

    float wxa = xs ? fxa : (1.0f - fxa);
    float wxb = xs ? fxb : (1.0f - fxb);
    float la  = (1.0f - alpha) * wxa;
    float lb  = alpha * wxb;
    float wa0 = la * (1.0f - fya), wa1 = la * fya;
    float wb0 = lb * (1.0f - fyb), wb1 = lb * fyb;

    float4 A = make_float4(0.f, 0.f, 0.f, 0.f);   // ch 8*cg .. +3
    float4 B = make_float4(0.f, 0.f, 0.f, 0.f);   // ch 8*cg+4 .. +7
#define ACC(V, W) {                                                  \
        float2 f0 = u2f2(V.x); A.x += (W) * f0.x; A.y += (W) * f0.y;  \
        float2 f1 = u2f2(V.y); A.z += (W) * f1.x; A.w += (W) * f1.y;  \
        float2 f2 = u2f2(V.z); B.x += (W) * f2.x; B.y += (W) * f2.y;  \
        float2 f3 = u2f2(V.w); B.z += (W) * f3.x; B.w += (W) * f3.y; }
    ACC(va0, wa0) ACC(va1, wa1) ACC(vb0, wb0) ACC(vb1, wb1)
#undef ACC

    // combine x0-side and x1-side partial sums (lane ^ 2)
    A.x += __shfl_xor_sync(0xFFFFFFFFu, A.x, 2);
    A.y += __shfl_xor_sync(0xFFFFFFFFu, A.y, 2);
    A.z += __shfl_xor_sync(0xFFFFFFFFu, A.z, 2);
    A.w += __shfl_xor_sync(0xFFFFFFFFu, A.w, 2);
    B.x += __shfl_xor_sync(0xFFFFFFFFu, B.x, 2);
    B.y += __shfl_xor_sync(0xFFFFFFFFu, B.y, 2);
    B.z += __shfl_xor_sync(0xFFFFFFFFu, B.z, 2);
    B.w += __shfl_xor_sync(0xFFFFFFFFu, B.w, 2);

    // lanes (xs,cg): (0,0)->ch0-3=A, (1,0)->ch4-7=B, (0,1)->ch8-11=A, (1,1)->ch12-15=B
    float4* o = reinterpret_cast<float4*>(out) + q * 4 + (cg * 2 + xs);
    __stcs(o, xs ? B : A);
}

// ---------------------------------------------------------------------------
extern "C" void kernel_launch(void* const* d_in, const int* in_sizes, int n_in,
                              void* d_out, int out_size) {
    const float* uv  = (const float*)d_in[0];
    const float* p   = (const float*)d_in[1];
    const float* tex = (const float*)d_in[2];
    float* out = (float*)d_out;
    int N = in_sizes[1];          // number of queries (p element count)

    // 1024 transpose blocks + ceil(174752/256)=683 mips blocks
    k_prep<<<1707, 256>>>(tex);
    int total = N * 4;
    k_sample<<<(total + 255) / 256, 256>>>(uv, p, out, N);
}

// round 12
// speedup vs baseline: 1.2168x; 1.1012x over previous
#include <cuda_runtime.h>
#include <cuda_fp16.h>

// ---------------------------------------------------------------------------
// Mipmapped texture sampling, GB300 — fp16 pyramid (32B/texel, HWC).
// Level i (i>=1) texel = 0.25 * 2x2 of base pixels at y0 = y*2^i + 2^(i-1) - 1
// (exact algebra of align_corners=False bilinear downsample by 2^i): mips are
// built straight from the fp32 input, fused with the transpose in one launch.
//
// Sample is L1tex-wavefront + issue bound. Wavefronts: the x0/x1 texel pair
// (contiguous 64B) is fetched by ONE warp-LDG across 4 lanes per query.
// Issue: the weighted accumulation runs entirely in half2 (HMUL2/HFMA2) on
// the loaded registers — no per-texel converts, half the FMA ops.
// x1/y1 are unclamped; their bilinear weight is exactly 0 when clamping
// would apply, and a zero pad on g_pyr covers the level-7 edge overrun.
// ---------------------------------------------------------------------------

#define NLEV 8

// 5,592,320 pyramid halves + 128 zero-pad halves for weight-0 edge overreads
__device__ __align__(16) __half g_pyr[5592448];

__constant__ int c_off[NLEV] = {
    0, 4194304, 5242880, 5505024, 5570560, 5586944, 5591040, 5592064
};

__device__ __forceinline__ unsigned f2u(float a, float b) {
    __half2 h = __floats2half2_rn(a, b);
    return *reinterpret_cast<const unsigned*>(&h);
}
__device__ __forceinline__ __half2 u2h(unsigned u) {
    return *reinterpret_cast<const __half2*>(&u);
}
__device__ __forceinline__ unsigned h2u(__half2 h) {
    return *reinterpret_cast<const unsigned*>(&h);
}
__device__ __forceinline__ float f2get(const float2& v, int j) {
    return j == 0 ? v.x : v.y;
}

// ---------------------------------------------------------------------------
// Fused prep kernel.
// Blocks [0,1024):    transpose. thread = (pixel-pair, channel-half):
//                     8 x LDG.64 plane loads, 2 x STG.128.
// Blocks [1024,1707): mips. thread = (texel, channel-half): level texel =
//                     0.25 * 2x2 of base fp32 pixels (reads tex directly).
// ---------------------------------------------------------------------------
__global__ void k_prep(const float* __restrict__ tex) {
    const int plane = 512 * 512;
    if (blockIdx.x < 1024) {
        int idx = blockIdx.x * blockDim.x + threadIdx.x;   // < 262144
        int t   = idx & 1;        // 0: channels 0-7, 1: channels 8-15
        int grp = idx >> 1;       // pixel pair index
        const int plane2 = plane / 2;
        const float2* src = reinterpret_cast<const float2*>(tex) + (8 * t) * plane2 + grp;

        float2 v0 = __ldg(src);
        float2 v1 = __ldg(src + plane2);
        float2 v2 = __ldg(src + 2 * plane2);
        float2 v3 = __ldg(src + 3 * plane2);
        float2 v4 = __ldg(src + 4 * plane2);
        float2 v5 = __ldg(src + 5 * plane2);
        float2 v6 = __ldg(src + 6 * plane2);
        float2 v7 = __ldg(src + 7 * plane2);

        uint4* base = reinterpret_cast<uint4*>(g_pyr);
#pragma unroll
        for (int j = 0; j < 2; j++) {
            uint4 a;
            a.x = f2u(f2get(v0, j), f2get(v1, j));
            a.y = f2u(f2get(v2, j), f2get(v3, j));
            a.z = f2u(f2get(v4, j), f2get(v5, j));
            a.w = f2u(f2get(v6, j), f2get(v7, j));
            base[(2 * grp + j) * 2 + t] = a;
        }
    } else {
        int idx = (blockIdx.x - 1024) * blockDim.x + threadIdx.x;
        if (idx >= 2 * 87376) return;
        int t   = idx & 1;
        int rem = idx >> 1;

        int l = 1;
#pragma unroll
        for (int i = 1; i < NLEV; i++) {
            int np = (512 >> i) * (512 >> i);
            if (rem < np) { l = i; break; }
            rem -= np;
        }
        int s  = 512 >> l;
        int x  = rem & (s - 1);
        int y  = rem >> (9 - l);
        int sc = 1 << l;
        int x0 = x * sc + (sc >> 1) - 1;
        int y0 = y * sc + (sc >> 1) - 1;

        const float* src = tex + (8 * t) * plane + y0 * 512 + x0;
#define AVG(c) (0.25f * (__ldg(src + (c) * plane)       + __ldg(src + (c) * plane + 1) + \
                         __ldg(src + (c) * plane + 512) + __ldg(src + (c) * plane + 513)))
        float a0 = AVG(0), a1 = AVG(1), a2 = AVG(2), a3 = AVG(3);
        float a4 = AVG(4), a5 = AVG(5), a6 = AVG(6), a7 = AVG(7);
#undef AVG
        uint4 r;
        r.x = f2u(a0, a1);
        r.y = f2u(a2, a3);
        r.z = f2u(a4, a5);
        r.w = f2u(a6, a7);
        reinterpret_cast<uint4*>(g_pyr + c_off[l])[(y * s + x) * 2 + t] = r;
    }
}

// ---------------------------------------------------------------------------
// Sample kernel. 4 threads/query: xs = t>>1 (x0 vs x1 texel), cg = t&1
// (channels 0-7 vs 8-15). Lane t loads bytes [16t,16t+16) of the 64B span
// [texel x0 | texel x1] for 4 (level,row) pairs -> 4 LDG.128 per thread,
// each warp-LDG touching ~1.25 lines per query. Accumulation in half2.
// ---------------------------------------------------------------------------
__device__ __forceinline__ void lvl_addr(int l, float gx, float gy, int t,
        const uint4*& r0, const uint4*& r1, float& fx, float& fy) {
    int   s  = 512 >> l;
    float fs = (float)(s - 1);
    float x = fminf(fmaxf((gx + 1.0f) * 0.5f * fs, 0.0f), fs);
    float y = fminf(fmaxf((gy + 1.0f) * 0.5f * fs, 0.0f), fs);
    int x0 = (int)x;             // trunc == floor (x >= 0)
    int y0 = (int)y;
    fx = x - (float)x0;          // 0 exactly when x1 would clamp
    fy = y - (float)y0;
    const uint4* b = reinterpret_cast<const uint4*>(g_pyr + c_off[l]);
    r0 = b + (y0 * s + x0) * 2 + t;   // lane t: 16B chunk of the 64B x0|x1 span
    r1 = r0 + 2 * s;                  // row y0+1 (unclamped; weight 0 at edge)
}

__global__ void k_sample(const float* __restrict__ uv,
                         const float* __restrict__ p,
                         float* __restrict__ out, int N) {
    int idx = blockIdx.x * blockDim.x + threadIdx.x;
    int q = idx >> 2;
    if (q >= N) return;
    int t  = idx & 3;
    int xs = t >> 1;      // 0: x0 texel, 1: x1 texel
    int cg = t & 1;       // 0: channels 0-7, 1: channels 8-15

    float2 uvq = __ldg(reinterpret_cast<const float2*>(uv) + q);
    float  pp  = __ldg(&p[q]);

    float lf = pp * (float)(NLEV - 1);
    int   l0 = min((int)lf, NLEV - 1);
    int   l1 = min(l0 + 1, NLEV - 1);
    float alpha = lf - (float)l0;

    float gx = 2.0f * uvq.x - 1.0f;
    float gy = 2.0f * uvq.y - 1.0f;

    const uint4 *a0, *a1, *b0, *b1;
    float fxa, fya, fxb, fyb;
    lvl_addr(l0, gx, gy, t, a0, a1, fxa, fya);
    lvl_addr(l1, gx, gy, t, b0, b1, fxb, fyb);

    // batch all 4 span loads (both levels, both rows)
    uint4 va0 = __ldg(a0);
    uint4 va1 = __ldg(a1);
    uint4 vb0 = __ldg(b0);
    uint4 vb1 = __ldg(b1);

    float wxa = xs ? fxa : (1.0f - fxa);
    float wxb = xs ? fxb : (1.0f - fxb);
    float la  = (1.0f - alpha) * wxa;
    float lb  = alpha * wxb;
    __half2 hw0 = __float2half2_rn(la * (1.0f - fya));
    __half2 hw1 = __float2half2_rn(la * fya);
    __half2 hw2 = __float2half2_rn(lb * (1.0f - fyb));
    __half2 hw3 = __float2half2_rn(lb * fyb);

    // half2 accumulation: 4 HMUL2 + 12 HFMA2, no per-texel converts
    __half2 A0 = __hmul2(u2h(va0.x), hw0);
    __half2 A1 = __hmul2(u2h(va0.y), hw0);
    __half2 A2 = __hmul2(u2h(va0.z), hw0);
    __half2 A3 = __hmul2(u2h(va0.w), hw0);
    A0 = __hfma2(u2h(va1.x), hw1, A0);
    A1 = __hfma2(u2h(va1.y), hw1, A1);
    A2 = __hfma2(u2h(va1.z), hw1, A2);
    A3 = __hfma2(u2h(va1.w), hw1, A3);
    A0 = __hfma2(u2h(vb0.x), hw2, A0);
    A1 = __hfma2(u2h(vb0.y), hw2, A1);
    A2 = __hfma2(u2h(vb0.z), hw2, A2);
    A3 = __hfma2(u2h(vb0.w), hw2, A3);
    A0 = __hfma2(u2h(vb1.x), hw3, A0);
    A1 = __hfma2(u2h(vb1.y), hw3, A1);
    A2 = __hfma2(u2h(vb1.z), hw3, A2);
    A3 = __hfma2(u2h(vb1.w), hw3, A3);

    // combine x0-side and x1-side partial sums (lane ^ 2)
    const unsigned FULL = 0xFFFFFFFFu;
    A0 = __hadd2(A0, u2h(__shfl_xor_sync(FULL, h2u(A0), 2)));
    A1 = __hadd2(A1, u2h(__shfl_xor_sync(FULL, h2u(A1), 2)));
    A2 = __hadd2(A2, u2h(__shfl_xor_sync(FULL, h2u(A2), 2)));
    A3 = __hadd2(A3, u2h(__shfl_xor_sync(FULL, h2u(A3), 2)));

    // lane (xs,cg) stores float4 k = cg*2+xs: xs=0 -> ch 8cg..+3 (A0,A1),
    // xs=1 -> ch 8cg+4..+7 (A2,A3)
    float2 f0 = __half22float2(xs ? A2 : A0);
    float2 f1 = __half22float2(xs ? A3 : A1);
    float4 r = make_float4(f0.x, f0.y, f1.x, f1.y);
    __stcs(reinterpret_cast<float4*>(out) + q * 4 + (cg * 2 + xs), r);
}

// ---------------------------------------------------------------------------
extern "C" void kernel_launch(void* const* d_in, const int* in_sizes, int n_in,
                              void* d_out, int out_size) {
    const float* uv  = (const float*)d_in[0];
    const float* p   = (const float*)d_in[1];
    const float* tex = (const float*)d_in[2];
    float* out = (float*)d_out;
    int N = in_sizes[1];          // number of queries (p element count)

    // 1024 transpose blocks + ceil(174752/256)=683 mips blocks
    k_prep<<<1707, 256>>>(tex);
    int total = N * 4;
    k_sample<<<(total + 255) / 256, 256>>>(uv, p, out, N);
}